// round 12
// baseline (speedup 1.0000x reference)
#include <cuda_runtime.h>
#include <cuda_fp16.h>
#include <float.h>

#define NN   50000
#define EE   600000
#define ETOT 650000
#define GG   50
#define INC  5
#define HID  64
#define OUTC 32
#define HEADS 4
#define BN_EPS 1e-5f
#define NSC  50176   // 49*1024 >= NN+1
#define FULLM 0xffffffffu

// ---------------- scratch (device globals) ----------------
__device__ __align__(16) unsigned g_hW[NN * 128];      // fp16 hW rows (half2 words)
__device__ __align__(16) float    g_es[NN * HEADS];
__device__ __align__(16) float    g_ed[NN * HEADS];
__device__ __align__(16) float    g_hn[NN * HID];      // aggregated (pre-BN), fp32
__device__ int g_cnt[NSC];
__device__ int g_bsum[49];
__device__ int g_boff[49];
__device__ int g_off[NN + 1];
__device__ int g_cur[NN];
__device__ int g_csr[ETOT];
__device__ double g_bnsum[HID];   // self-zeroing (bn_finalize)
__device__ double g_bnsq [HID];
__device__ float  g_scale[HID];
__device__ float  g_shift[HID];

__device__ __forceinline__ float lrelu(float v) { return v > 0.f ? v : 0.2f * v; }

// packed fp32x2 helpers (sm_103a FFMA2 path — ptxas never auto-fuses)
#define PACK_DUP_F32X2(d, s) \
    asm("mov.b64 %0, {%1, %1};" : "=l"(d) : "r"(__float_as_uint(s)))
#define FMA_F32X2(acc, a, b) \
    asm("fma.rn.f32x2 %0, %1, %2, %0;" : "+l"(acc) : "l"(a), "l"(b))
#define UNPACK_F32X2_(lo, hi, in) \
    asm("mov.b64 {%0, %1}, %2;" : "=f"(lo), "=f"(hi) : "l"(in))

// ---------------- CSR build ----------------
__global__ void k_hist(const int* __restrict__ ei) {
    int e = blockIdx.x * blockDim.x + threadIdx.x;
    if (e >= ETOT) return;
    int d = (e < EE) ? ei[EE + e] : (e - EE);
    atomicAdd(&g_cnt[d], 1);
}
__global__ void k_scan_a() {   // 49 blocks x 1024
    __shared__ int sm[1024];
    int t = threadIdx.x;
    sm[t] = g_cnt[blockIdx.x * 1024 + t];
    __syncthreads();
    for (int o = 512; o; o >>= 1) {
        if (t < o) sm[t] += sm[t + o];
        __syncthreads();
    }
    if (t == 0) g_bsum[blockIdx.x] = sm[0];
}
__global__ void k_scan_b() {
    int acc = 0;
    for (int b = 0; b < 49; b++) { g_boff[b] = acc; acc += g_bsum[b]; }
}
__global__ void k_scan_c() {   // inclusive scan -> exclusive; self-zeroes g_cnt
    __shared__ int sm[1024];
    int t = threadIdx.x;
    int i = blockIdx.x * 1024 + t;
    int v = g_cnt[i];
    g_cnt[i] = 0;                      // restore precondition for next launch
    sm[t] = v;
    __syncthreads();
    for (int o = 1; o < 1024; o <<= 1) {
        int u = (t >= o) ? sm[t - o] : 0;
        __syncthreads();
        sm[t] += u;
        __syncthreads();
    }
    int ex = g_boff[blockIdx.x] + sm[t] - v;
    if (i <= NN) g_off[i] = ex;
    if (i < NN)  g_cur[i] = ex;
}
__global__ void k_fill(const int* __restrict__ ei) {
    int e = blockIdx.x * blockDim.x + threadIdx.x;
    if (e >= ETOT) return;
    int s, d;
    if (e < EE) { s = ei[e]; d = ei[EE + e]; } else { s = d = e - EE; }
    int pos = atomicAdd(&g_cur[d], 1);
    g_csr[pos] = s;
}

// ---------------- transform: h@W (packed f32x2 FMA, fp16 store) + fused encoder/BN-in + es/ed ----
// (R7 version — measured 349us)
template <int DOUT, int MODE>
__global__ void __launch_bounds__(256)
k_transform2(const float* __restrict__ in, const float* __restrict__ W,
             const float* __restrict__ as_, const float* __restrict__ ad_,
             const float* __restrict__ enc_w, const float* __restrict__ enc_b) {
    constexpr int HD    = 4 * DOUT;
    constexpr int COLT  = HD / 4;
    constexpr int NGRP  = 256 / COLT;
    constexpr int NODES = NGRP * 8;
    constexpr int LPH   = DOUT / 4;
    __shared__ float sh[NODES * HID];

    int t = threadIdx.x;
    int nbase = blockIdx.x * NODES;

    if (MODE == 0) {
        __shared__ float sx[NODES * INC];
        for (int i = t; i < NODES * INC; i += 256) {
            int n = nbase + i / INC;
            sx[i] = (n < NN) ? in[n * INC + i % INC] : 0.f;
        }
        __syncthreads();
        for (int i = t; i < NODES * HID; i += 256) {
            int nl = i / HID, k = i % HID;
            float acc = enc_b[k];
#pragma unroll
            for (int j = 0; j < INC; j++) acc = fmaf(sx[nl * INC + j], enc_w[j * HID + k], acc);
            sh[i] = acc;
        }
    } else {
        for (int i = t; i < NODES * HID; i += 256) {
            int n = nbase + i / HID;
            int k = i % HID;
            float v = 0.f;
            if (n < NN) {
                v = in[n * HID + k];
                v = fmaxf(fmaf(g_scale[k], v, g_shift[k]), 0.f);
            }
            sh[i] = v;
        }
    }
    __syncthreads();

    int tx = t % COLT;
    int g  = t / COLT;
    int j0 = g * 8;

    unsigned long long accp[8][2];
#pragma unroll
    for (int j = 0; j < 8; j++) { accp[j][0] = 0ull; accp[j][1] = 0ull; }

#pragma unroll 2
    for (int k = 0; k < HID; k += 2) {
        ulonglong2 w0 = *(const ulonglong2*)&W[k * HD + 4 * tx];
        ulonglong2 w1 = *(const ulonglong2*)&W[(k + 1) * HD + 4 * tx];
#pragma unroll
        for (int j = 0; j < 8; j++) {
            float2 hv = *(const float2*)&sh[(j0 + j) * HID + k];
            unsigned long long h0, h1;
            PACK_DUP_F32X2(h0, hv.x);
            PACK_DUP_F32X2(h1, hv.y);
            FMA_F32X2(accp[j][0], h0, w0.x);
            FMA_F32X2(accp[j][1], h0, w0.y);
            FMA_F32X2(accp[j][0], h1, w1.x);
            FMA_F32X2(accp[j][1], h1, w1.y);
        }
    }

    float4 as4 = *(const float4*)&as_[4 * tx];
    float4 ad4 = *(const float4*)&ad_[4 * tx];
    int head = (4 * tx) / DOUT;

#pragma unroll
    for (int j = 0; j < 8; j++) {
        float4 acc;
        UNPACK_F32X2_(acc.x, acc.y, accp[j][0]);
        UNPACK_F32X2_(acc.z, acc.w, accp[j][1]);
        int n = nbase + j0 + j;
        if (n < NN) {
            __half2 p0 = __floats2half2_rn(acc.x, acc.y);
            __half2 p1 = __floats2half2_rn(acc.z, acc.w);
            uint2 u;
            u.x = *reinterpret_cast<unsigned*>(&p0);
            u.y = *reinterpret_cast<unsigned*>(&p1);
            *(uint2*)&g_hW[(size_t)n * (HD / 2) + 2 * tx] = u;
        }
        float pes = acc.x * as4.x + acc.y * as4.y + acc.z * as4.z + acc.w * as4.w;
        float ped = acc.x * ad4.x + acc.y * ad4.y + acc.z * ad4.z + acc.w * ad4.w;
#pragma unroll
        for (int o = LPH / 2; o; o >>= 1) {
            pes += __shfl_xor_sync(FULLM, pes, o);
            ped += __shfl_xor_sync(FULLM, ped, o);
        }
        if ((tx % LPH) == 0 && n < NN) {
            g_es[n * 4 + head] = pes;
            g_ed[n * 4 + head] = ped;
        }
    }
}

// ---------------- fused GAT aggregation: warp/dst, depth-2 pipelined gather ---------------------
__global__ void __launch_bounds__(256)
k_agg64() {
    int warp = threadIdx.x >> 5, lane = threadIdx.x & 31;
    int n = blockIdx.x * 8 + warp;
    if (n >= NN) return;
    int beg = g_off[n], end = g_off[n + 1];   // deg >= 1 (self-loop)

    float edh = (lane < 4) ? g_ed[n * 4 + lane] : 0.f;
    const uint4* hw = (const uint4*)g_hW;

    float sacc = 0.f;
    float a[8];
#pragma unroll
    for (int i = 0; i < 8; i++) a[i] = 0.f;

    // prologue: edges beg, beg+1 loaded (or duplicated); csr for beg+2 in flight
    int   s0 = __ldg(&g_csr[beg]);
    uint4 v0 = hw[(size_t)s0 * 32 + lane];
    float e0 = (lane < 4) ? __ldg(&g_es[s0 * 4 + lane]) : 0.f;
    uint4 v1 = v0;
    float e1 = e0;
    if (beg + 1 < end) {
        int s1 = __ldg(&g_csr[beg + 1]);
        v1 = hw[(size_t)s1 * 32 + lane];
        e1 = (lane < 4) ? __ldg(&g_es[s1 * 4 + lane]) : 0.f;
    }
    int sN = (beg + 2 < end) ? __ldg(&g_csr[beg + 2]) : 0;

    for (int i = beg; i < end; i++) {
        uint4 v2 = v1;
        float e2 = e1;
        int   s3 = sN;
        if (i + 2 < end) {                       // issue edge-(i+2) loads (addr sN ready 2 iters ago)
            v2 = hw[(size_t)sN * 32 + lane];
            e2 = (lane < 4) ? __ldg(&g_es[sN * 4 + lane]) : 0.f;
            if (i + 3 < end) s3 = __ldg(&g_csr[i + 3]);
        }
        float ex = 0.f;
        if (lane < 4) {
            ex = expf(lrelu(e0 + edh));
            sacc += ex;
        }
        float exA = __shfl_sync(FULLM, ex, lane >> 3);
        float2 f0 = __half22float2(*(__half2*)&v0.x);
        float2 f1 = __half22float2(*(__half2*)&v0.y);
        float2 f2 = __half22float2(*(__half2*)&v0.z);
        float2 f3 = __half22float2(*(__half2*)&v0.w);
        a[0] = fmaf(f0.x, exA, a[0]); a[1] = fmaf(f0.y, exA, a[1]);
        a[2] = fmaf(f1.x, exA, a[2]); a[3] = fmaf(f1.y, exA, a[3]);
        a[4] = fmaf(f2.x, exA, a[4]); a[5] = fmaf(f2.y, exA, a[5]);
        a[6] = fmaf(f3.x, exA, a[6]); a[7] = fmaf(f3.y, exA, a[7]);
        v0 = v1; e0 = e1;
        v1 = v2; e1 = e2;
        sN = s3;
    }

    float sA = __shfl_sync(FULLM, sacc, lane >> 3) + 1e-16f;
    float inv = 0.25f / sA;
#pragma unroll
    for (int i = 0; i < 8; i++) a[i] *= inv;
#pragma unroll
    for (int i = 0; i < 8; i++) {
        a[i] += __shfl_xor_sync(FULLM, a[i], 8);
        a[i] += __shfl_xor_sync(FULLM, a[i], 16);
    }
    if (lane < 8) {
        *(float4*)&g_hn[n * 64 + 8 * lane]     = make_float4(a[0], a[1], a[2], a[3]);
        *(float4*)&g_hn[n * 64 + 8 * lane + 4] = make_float4(a[4], a[5], a[6], a[7]);
    }
}

__global__ void __launch_bounds__(256)
k_agg32() {
    int warp = threadIdx.x >> 5, lane = threadIdx.x & 31;
    int n = blockIdx.x * 8 + warp;
    if (n >= NN) return;
    int beg = g_off[n], end = g_off[n + 1];

    float edh = (lane < 4) ? g_ed[n * 4 + lane] : 0.f;
    const uint2* hw = (const uint2*)g_hW;

    float sacc = 0.f;
    float a[4];
#pragma unroll
    for (int i = 0; i < 4; i++) a[i] = 0.f;

    int   s0 = __ldg(&g_csr[beg]);
    uint2 v0 = hw[(size_t)s0 * 32 + lane];
    float e0 = (lane < 4) ? __ldg(&g_es[s0 * 4 + lane]) : 0.f;
    uint2 v1 = v0;
    float e1 = e0;
    if (beg + 1 < end) {
        int s1 = __ldg(&g_csr[beg + 1]);
        v1 = hw[(size_t)s1 * 32 + lane];
        e1 = (lane < 4) ? __ldg(&g_es[s1 * 4 + lane]) : 0.f;
    }
    int sN = (beg + 2 < end) ? __ldg(&g_csr[beg + 2]) : 0;

    for (int i = beg; i < end; i++) {
        uint2 v2 = v1;
        float e2 = e1;
        int   s3 = sN;
        if (i + 2 < end) {
            v2 = hw[(size_t)sN * 32 + lane];
            e2 = (lane < 4) ? __ldg(&g_es[sN * 4 + lane]) : 0.f;
            if (i + 3 < end) s3 = __ldg(&g_csr[i + 3]);
        }
        float ex = 0.f;
        if (lane < 4) {
            ex = expf(lrelu(e0 + edh));
            sacc += ex;
        }
        float exA = __shfl_sync(FULLM, ex, lane >> 3);
        float2 f0 = __half22float2(*(__half2*)&v0.x);
        float2 f1 = __half22float2(*(__half2*)&v0.y);
        a[0] = fmaf(f0.x, exA, a[0]); a[1] = fmaf(f0.y, exA, a[1]);
        a[2] = fmaf(f1.x, exA, a[2]); a[3] = fmaf(f1.y, exA, a[3]);
        v0 = v1; e0 = e1;
        v1 = v2; e1 = e2;
        sN = s3;
    }

    float sA = __shfl_sync(FULLM, sacc, lane >> 3) + 1e-16f;
    float inv = 0.25f / sA;
#pragma unroll
    for (int i = 0; i < 4; i++) a[i] *= inv;
#pragma unroll
    for (int i = 0; i < 4; i++) {
        a[i] += __shfl_xor_sync(FULLM, a[i], 8);
        a[i] += __shfl_xor_sync(FULLM, a[i], 16);
    }
    if (lane < 8)
        *(float4*)&g_hn[n * 32 + 4 * lane] = make_float4(a[0], a[1], a[2], a[3]);
}

// ---------------- BatchNorm (R7 style: separate partial + finalize) ----------------
template <int DOUT>
__global__ void __launch_bounds__(256)
k_bn_partial() {
    int tid = threadIdx.x;
    int c = tid % DOUT;
    float s = 0.f, q = 0.f;
    for (long i = (long)blockIdx.x * blockDim.x + tid; i < (long)NN * DOUT;
         i += (long)gridDim.x * blockDim.x) {
        float v = g_hn[i];
        s += v; q += v * v;
    }
    __shared__ float sm[256], qm[256];
    sm[tid] = s; qm[tid] = q;
    __syncthreads();
    for (int off = 128; off >= DOUT; off >>= 1) {
        if (tid < off) { sm[tid] += sm[tid + off]; qm[tid] += qm[tid + off]; }
        __syncthreads();
    }
    if (tid < DOUT) {
        atomicAdd(&g_bnsum[c], (double)sm[tid]);
        atomicAdd(&g_bnsq[c],  (double)qm[tid]);
    }
}
template <int DOUT>
__global__ void k_bn_finalize(const float* __restrict__ gamma, const float* __restrict__ beta) {
    int c = threadIdx.x;
    if (c >= DOUT) return;
    float mean = (float)(g_bnsum[c] / (double)NN);
    float var  = (float)(g_bnsq[c] / (double)NN) - mean * mean;
    var = fmaxf(var, 0.f);
    float sc = gamma[c] * rsqrtf(var + BN_EPS);
    g_scale[c] = sc;
    g_shift[c] = beta[c] - mean * sc;
    g_bnsum[c] = 0.0;
    g_bnsq[c]  = 0.0;
}

// ---------------- fused: final BN apply + per-graph pooling + gemb + both heads ----------------
__global__ void __launch_bounds__(256)
k_pool_fused(const int* __restrict__ batch, float* __restrict__ out_h,
             float* __restrict__ out_gemb, float* __restrict__ out_eth,
             float* __restrict__ out_man,
             const float* __restrict__ ew1, const float* __restrict__ eb1,
             const float* __restrict__ ew2, const float* __restrict__ eb2,
             const float* __restrict__ mw1, const float* __restrict__ mb1,
             const float* __restrict__ mw2, const float* __restrict__ mb2) {
    int g = blockIdx.x;
    int t = threadIdx.x;
    int l = 0, r = NN;
    while (l < r) { int m = (l + r) >> 1; if (batch[m] < g) l = m + 1; else r = m; }
    int s0 = l;
    l = s0; r = NN;
    while (l < r) { int m = (l + r) >> 1; if (batch[m] < g + 1) l = m + 1; else r = m; }
    int s1 = l;

    int c = t % 32, row = t / 32;
    float sc = g_scale[c], shf = g_shift[c];
    float sum = 0.f, mx = -FLT_MAX;
    for (int n = s0 + row; n < s1; n += 8) {
        float v = fmaf(sc, g_hn[n * 32 + c], shf);
        out_h[n * 32 + c] = v;
        sum += v;
        mx = fmaxf(mx, v);
    }
    __shared__ float ssum[256], smax[256];
    __shared__ float ge[32];
    ssum[t] = sum; smax[t] = mx;
    __syncthreads();
    for (int o = 128; o >= 32; o >>= 1) {
        if (t < o) { ssum[t] += ssum[t + o]; smax[t] = fmaxf(smax[t], smax[t + o]); }
        __syncthreads();
    }
    if (t < 32) {
        float cnt = (float)(s1 - s0);
        float sm = ssum[t];
        float mean = sm / fmaxf(cnt, 1.f);
        float mxv = (cnt > 0.f) ? smax[t] : 0.f;
        float v = (mean + mxv + sm) * (1.f / 3.f);
        out_gemb[g * 32 + t] = v;
        ge[t] = v;
    }
    __syncthreads();
    if (t < 32) {
        const float* w1 = (t < 16) ? ew1 : mw1;
        const float* b1 = (t < 16) ? eb1 : mb1;
        const float* w2 = (t < 16) ? ew2 : mw2;
        const float* b2 = (t < 16) ? eb2 : mb2;
        int j = t & 15;
        float a = b1[j];
#pragma unroll
        for (int k = 0; k < 32; k++) a = fmaf(ge[k], w1[k * 16 + j], a);
        float contrib = fmaxf(a, 0.f) * w2[j];
#pragma unroll
        for (int o = 8; o; o >>= 1) contrib += __shfl_xor_sync(FULLM, contrib, o);
        if (j == 0) {
            float oo = contrib + b2[0];
            float sig = 1.f / (1.f + expf(-oo));
            if (t < 16) out_eth[g] = sig; else out_man[g] = sig;
        }
    }
}

// ---------------- host ----------------
extern "C" void kernel_launch(void* const* d_in, const int* in_sizes, int n_in,
                              void* d_out, int out_size) {
    const float* x      = (const float*)d_in[0];
    const int*   ei     = (const int*)d_in[1];
    const int*   batch  = (const int*)d_in[2];
    const float* enc_w  = (const float*)d_in[3];
    const float* enc_b  = (const float*)d_in[4];
    const float* W0 = (const float*)d_in[5],  *A0s = (const float*)d_in[6],  *A0d = (const float*)d_in[7];
    const float* G0 = (const float*)d_in[9],  *B0  = (const float*)d_in[10];
    const float* W1 = (const float*)d_in[11], *A1s = (const float*)d_in[12], *A1d = (const float*)d_in[13];
    const float* G1 = (const float*)d_in[15], *B1  = (const float*)d_in[16];
    const float* W2 = (const float*)d_in[17], *A2s = (const float*)d_in[18], *A2d = (const float*)d_in[19];
    const float* G2 = (const float*)d_in[21], *B2  = (const float*)d_in[22];
    const float* ew1 = (const float*)d_in[23], *eb1 = (const float*)d_in[24];
    const float* ew2 = (const float*)d_in[25], *eb2 = (const float*)d_in[26];
    const float* mw1 = (const float*)d_in[27], *mb1 = (const float*)d_in[28];
    const float* mw2 = (const float*)d_in[29], *mb2 = (const float*)d_in[30];

    float* out      = (float*)d_out;
    float* out_h    = out;
    float* out_gemb = out + (size_t)NN * OUTC;
    float* out_eth  = out_gemb + GG * OUTC;
    float* out_man  = out_eth + GG;

    void* phn;
    cudaGetSymbolAddress(&phn, g_hn);

    // CSR build (g_cnt self-zeroing via k_scan_c; zero at module load)
    k_hist<<<(ETOT + 255) / 256, 256>>>(ei);
    k_scan_a<<<49, 1024>>>();
    k_scan_b<<<1, 1>>>();
    k_scan_c<<<49, 1024>>>();
    k_fill<<<(ETOT + 255) / 256, 256>>>(ei);

    // Layer 0 (encoder fused into transform input stage)
    k_transform2<64, 0><<<(NN + 31) / 32, 256>>>(x, W0, A0s, A0d, enc_w, enc_b);
    k_agg64<<<(NN + 7) / 8, 256>>>();
    k_bn_partial<64><<<296, 256>>>();
    k_bn_finalize<64><<<1, 64>>>(G0, B0);

    // Layer 1
    k_transform2<64, 1><<<(NN + 31) / 32, 256>>>((const float*)phn, W1, A1s, A1d, enc_w, enc_b);
    k_agg64<<<(NN + 7) / 8, 256>>>();
    k_bn_partial<64><<<296, 256>>>();
    k_bn_finalize<64><<<1, 64>>>(G1, B1);

    // Layer 2
    k_transform2<32, 1><<<(NN + 63) / 64, 256>>>((const float*)phn, W2, A2s, A2d, enc_w, enc_b);
    k_agg32<<<(NN + 7) / 8, 256>>>();
    k_bn_partial<32><<<296, 256>>>();
    k_bn_finalize<32><<<1, 32>>>(G2, B2);

    // Fused BN apply + pooling + gemb + heads
    k_pool_fused<<<GG, 256>>>(batch, out_h, out_gemb, out_eth, out_man,
                              ew1, eb1, ew2, eb2, mw1, mb1, mw2, mb2);
}

// round 13
// speedup vs baseline: 1.0490x; 1.0490x over previous
#include <cuda_runtime.h>
#include <cuda_fp16.h>
#include <float.h>

#define NN   50000
#define EE   600000
#define ETOT 650000
#define GG   50
#define INC  5
#define HID  64
#define OUTC 32
#define HEADS 4
#define BN_EPS 1e-5f
#define NSC  50176   // 49*1024 >= NN+1
#define FULLM 0xffffffffu

// ---------------- scratch (device globals) ----------------
__device__ __align__(16) unsigned g_hW[NN * 128];      // fp16 hW rows (half2 words)
__device__ __align__(16) float    g_es[NN * HEADS];
__device__ __align__(16) float    g_ed[NN * HEADS];
__device__ __align__(16) float    g_hn[NN * HID];      // aggregated (pre-BN), fp32
__device__ int g_cnt[NSC];
__device__ int g_bsum[49];
__device__ int g_boff[49];
__device__ int g_off[NN + 1];
__device__ int g_cur[NN];
__device__ int g_csr[ETOT];
__device__ double g_bnsum[HID];   // self-zeroing (fused finalize)
__device__ double g_bnsq [HID];
__device__ float  g_scale[HID];
__device__ float  g_shift[HID];
__device__ unsigned g_tick;       // zero-init; self-resetting ticket

__device__ __forceinline__ float lrelu(float v) { return v > 0.f ? v : 0.2f * v; }

// packed fp32x2 helpers (sm_103a FFMA2 path — ptxas never auto-fuses)
#define PACK_DUP_F32X2(d, s) \
    asm("mov.b64 %0, {%1, %1};" : "=l"(d) : "r"(__float_as_uint(s)))
#define FMA_F32X2(acc, a, b) \
    asm("fma.rn.f32x2 %0, %1, %2, %0;" : "+l"(acc) : "l"(a), "l"(b))
#define UNPACK_F32X2_(lo, hi, in) \
    asm("mov.b64 {%0, %1}, %2;" : "=f"(lo), "=f"(hi) : "l"(in))

// release/acquire ticket — NO __threadfence (avoids CCTL.IVALL L1 flush)
__device__ __forceinline__ unsigned ticket_acq_rel(unsigned* addr) {
    unsigned old;
    asm volatile("atom.acq_rel.gpu.global.add.u32 %0, [%1], 1;"
                 : "=r"(old) : "l"(addr) : "memory");
    return old;
}
__device__ __forceinline__ double ld_cg_f64(const double* p) {
    double v;
    asm volatile("ld.global.cg.f64 %0, [%1];" : "=d"(v) : "l"(p));
    return v;
}

// ---------------- CSR build ----------------
__global__ void k_hist(const int* __restrict__ ei) {
    int e = blockIdx.x * blockDim.x + threadIdx.x;
    if (e >= ETOT) return;
    int d = (e < EE) ? ei[EE + e] : (e - EE);
    atomicAdd(&g_cnt[d], 1);
}
__global__ void k_scan_a() {   // 49 blocks x 1024
    __shared__ int sm[1024];
    int t = threadIdx.x;
    sm[t] = g_cnt[blockIdx.x * 1024 + t];
    __syncthreads();
    for (int o = 512; o; o >>= 1) {
        if (t < o) sm[t] += sm[t + o];
        __syncthreads();
    }
    if (t == 0) g_bsum[blockIdx.x] = sm[0];
}
__global__ void k_scan_b() {
    int acc = 0;
    for (int b = 0; b < 49; b++) { g_boff[b] = acc; acc += g_bsum[b]; }
}
__global__ void k_scan_c() {   // inclusive scan -> exclusive; self-zeroes g_cnt
    __shared__ int sm[1024];
    int t = threadIdx.x;
    int i = blockIdx.x * 1024 + t;
    int v = g_cnt[i];
    g_cnt[i] = 0;                      // restore precondition for next launch
    sm[t] = v;
    __syncthreads();
    for (int o = 1; o < 1024; o <<= 1) {
        int u = (t >= o) ? sm[t - o] : 0;
        __syncthreads();
        sm[t] += u;
        __syncthreads();
    }
    int ex = g_boff[blockIdx.x] + sm[t] - v;
    if (i <= NN) g_off[i] = ex;
    if (i < NN)  g_cur[i] = ex;
}
__global__ void k_fill(const int* __restrict__ ei) {
    int e = blockIdx.x * blockDim.x + threadIdx.x;
    if (e >= ETOT) return;
    int s, d;
    if (e < EE) { s = ei[e]; d = ei[EE + e]; } else { s = d = e - EE; }
    int pos = atomicAdd(&g_cur[d], 1);
    g_csr[pos] = s;
}

// ---------------- transform: h@W (packed f32x2 FMA, fp16 store) + fused encoder/BN-in + es/ed ----
template <int DOUT, int MODE>
__global__ void __launch_bounds__(256)
k_transform2(const float* __restrict__ in, const float* __restrict__ W,
             const float* __restrict__ as_, const float* __restrict__ ad_,
             const float* __restrict__ enc_w, const float* __restrict__ enc_b) {
    constexpr int HD    = 4 * DOUT;
    constexpr int COLT  = HD / 4;
    constexpr int NGRP  = 256 / COLT;
    constexpr int NODES = NGRP * 8;
    constexpr int LPH   = DOUT / 4;
    __shared__ float sh[NODES * HID];

    int t = threadIdx.x;
    int nbase = blockIdx.x * NODES;

    if (MODE == 0) {
        __shared__ float sx[NODES * INC];
        for (int i = t; i < NODES * INC; i += 256) {
            int n = nbase + i / INC;
            sx[i] = (n < NN) ? in[n * INC + i % INC] : 0.f;
        }
        __syncthreads();
        for (int i = t; i < NODES * HID; i += 256) {
            int nl = i / HID, k = i % HID;
            float acc = enc_b[k];
#pragma unroll
            for (int j = 0; j < INC; j++) acc = fmaf(sx[nl * INC + j], enc_w[j * HID + k], acc);
            sh[i] = acc;
        }
    } else {
        for (int i = t; i < NODES * HID; i += 256) {
            int n = nbase + i / HID;
            int k = i % HID;
            float v = 0.f;
            if (n < NN) {
                v = in[n * HID + k];
                v = fmaxf(fmaf(g_scale[k], v, g_shift[k]), 0.f);
            }
            sh[i] = v;
        }
    }
    __syncthreads();

    int tx = t % COLT;
    int g  = t / COLT;
    int j0 = g * 8;

    unsigned long long accp[8][2];
#pragma unroll
    for (int j = 0; j < 8; j++) { accp[j][0] = 0ull; accp[j][1] = 0ull; }

#pragma unroll 2
    for (int k = 0; k < HID; k += 2) {
        ulonglong2 w0 = *(const ulonglong2*)&W[k * HD + 4 * tx];
        ulonglong2 w1 = *(const ulonglong2*)&W[(k + 1) * HD + 4 * tx];
#pragma unroll
        for (int j = 0; j < 8; j++) {
            float2 hv = *(const float2*)&sh[(j0 + j) * HID + k];
            unsigned long long h0, h1;
            PACK_DUP_F32X2(h0, hv.x);
            PACK_DUP_F32X2(h1, hv.y);
            FMA_F32X2(accp[j][0], h0, w0.x);
            FMA_F32X2(accp[j][1], h0, w0.y);
            FMA_F32X2(accp[j][0], h1, w1.x);
            FMA_F32X2(accp[j][1], h1, w1.y);
        }
    }

    float4 as4 = *(const float4*)&as_[4 * tx];
    float4 ad4 = *(const float4*)&ad_[4 * tx];
    int head = (4 * tx) / DOUT;

#pragma unroll
    for (int j = 0; j < 8; j++) {
        float4 acc;
        UNPACK_F32X2_(acc.x, acc.y, accp[j][0]);
        UNPACK_F32X2_(acc.z, acc.w, accp[j][1]);
        int n = nbase + j0 + j;
        if (n < NN) {
            __half2 p0 = __floats2half2_rn(acc.x, acc.y);
            __half2 p1 = __floats2half2_rn(acc.z, acc.w);
            uint2 u;
            u.x = *reinterpret_cast<unsigned*>(&p0);
            u.y = *reinterpret_cast<unsigned*>(&p1);
            *(uint2*)&g_hW[(size_t)n * (HD / 2) + 2 * tx] = u;
        }
        float pes = acc.x * as4.x + acc.y * as4.y + acc.z * as4.z + acc.w * as4.w;
        float ped = acc.x * ad4.x + acc.y * ad4.y + acc.z * ad4.z + acc.w * ad4.w;
#pragma unroll
        for (int o = LPH / 2; o; o >>= 1) {
            pes += __shfl_xor_sync(FULLM, pes, o);
            ped += __shfl_xor_sync(FULLM, ped, o);
        }
        if ((tx % LPH) == 0 && n < NN) {
            g_es[n * 4 + head] = pes;
            g_ed[n * 4 + head] = ped;
        }
    }
}

// ---------------- fused GAT aggregation (R11 depth-1 pipeline — best measured) ------------------
__global__ void __launch_bounds__(256)
k_agg64() {
    int warp = threadIdx.x >> 5, lane = threadIdx.x & 31;
    int n = blockIdx.x * 8 + warp;
    if (n >= NN) return;
    int beg = g_off[n], end = g_off[n + 1];   // deg >= 1 (self-loop)

    float edh = (lane < 4) ? g_ed[n * 4 + lane] : 0.f;
    const uint4* hw = (const uint4*)g_hW;

    float sacc = 0.f;
    float a[8];
#pragma unroll
    for (int i = 0; i < 8; i++) a[i] = 0.f;

    int   s0 = __ldg(&g_csr[beg]);
    uint4 v0 = hw[(size_t)s0 * 32 + lane];
    float e0 = (lane < 4) ? __ldg(&g_es[s0 * 4 + lane]) : 0.f;
    int   s1 = (beg + 1 < end) ? __ldg(&g_csr[beg + 1]) : 0;

    for (int i = beg; i < end; i++) {
        uint4 v1 = v0;
        float e1 = e0;
        int   s2 = s1;
        if (i + 1 < end) {
            v1 = hw[(size_t)s1 * 32 + lane];
            e1 = (lane < 4) ? __ldg(&g_es[s1 * 4 + lane]) : 0.f;
            if (i + 2 < end) s2 = __ldg(&g_csr[i + 2]);
        }
        float ex = 0.f;
        if (lane < 4) {
            ex = expf(lrelu(e0 + edh));
            sacc += ex;
        }
        float exA = __shfl_sync(FULLM, ex, lane >> 3);
        float2 f0 = __half22float2(*(__half2*)&v0.x);
        float2 f1 = __half22float2(*(__half2*)&v0.y);
        float2 f2 = __half22float2(*(__half2*)&v0.z);
        float2 f3 = __half22float2(*(__half2*)&v0.w);
        a[0] = fmaf(f0.x, exA, a[0]); a[1] = fmaf(f0.y, exA, a[1]);
        a[2] = fmaf(f1.x, exA, a[2]); a[3] = fmaf(f1.y, exA, a[3]);
        a[4] = fmaf(f2.x, exA, a[4]); a[5] = fmaf(f2.y, exA, a[5]);
        a[6] = fmaf(f3.x, exA, a[6]); a[7] = fmaf(f3.y, exA, a[7]);
        v0 = v1; e0 = e1; s1 = s2;
    }

    float sA = __shfl_sync(FULLM, sacc, lane >> 3) + 1e-16f;
    float inv = 0.25f / sA;
#pragma unroll
    for (int i = 0; i < 8; i++) a[i] *= inv;
#pragma unroll
    for (int i = 0; i < 8; i++) {
        a[i] += __shfl_xor_sync(FULLM, a[i], 8);
        a[i] += __shfl_xor_sync(FULLM, a[i], 16);
    }
    if (lane < 8) {
        *(float4*)&g_hn[n * 64 + 8 * lane]     = make_float4(a[0], a[1], a[2], a[3]);
        *(float4*)&g_hn[n * 64 + 8 * lane + 4] = make_float4(a[4], a[5], a[6], a[7]);
    }
}

__global__ void __launch_bounds__(256)
k_agg32() {
    int warp = threadIdx.x >> 5, lane = threadIdx.x & 31;
    int n = blockIdx.x * 8 + warp;
    if (n >= NN) return;
    int beg = g_off[n], end = g_off[n + 1];

    float edh = (lane < 4) ? g_ed[n * 4 + lane] : 0.f;
    const uint2* hw = (const uint2*)g_hW;

    float sacc = 0.f;
    float a[4];
#pragma unroll
    for (int i = 0; i < 4; i++) a[i] = 0.f;

    int   s0 = __ldg(&g_csr[beg]);
    uint2 v0 = hw[(size_t)s0 * 32 + lane];
    float e0 = (lane < 4) ? __ldg(&g_es[s0 * 4 + lane]) : 0.f;
    int   s1 = (beg + 1 < end) ? __ldg(&g_csr[beg + 1]) : 0;

    for (int i = beg; i < end; i++) {
        uint2 v1 = v0;
        float e1 = e0;
        int   s2 = s1;
        if (i + 1 < end) {
            v1 = hw[(size_t)s1 * 32 + lane];
            e1 = (lane < 4) ? __ldg(&g_es[s1 * 4 + lane]) : 0.f;
            if (i + 2 < end) s2 = __ldg(&g_csr[i + 2]);
        }
        float ex = 0.f;
        if (lane < 4) {
            ex = expf(lrelu(e0 + edh));
            sacc += ex;
        }
        float exA = __shfl_sync(FULLM, ex, lane >> 3);
        float2 f0 = __half22float2(*(__half2*)&v0.x);
        float2 f1 = __half22float2(*(__half2*)&v0.y);
        a[0] = fmaf(f0.x, exA, a[0]); a[1] = fmaf(f0.y, exA, a[1]);
        a[2] = fmaf(f1.x, exA, a[2]); a[3] = fmaf(f1.y, exA, a[3]);
        v0 = v1; e0 = e1; s1 = s2;
    }

    float sA = __shfl_sync(FULLM, sacc, lane >> 3) + 1e-16f;
    float inv = 0.25f / sA;
#pragma unroll
    for (int i = 0; i < 4; i++) a[i] *= inv;
#pragma unroll
    for (int i = 0; i < 4; i++) {
        a[i] += __shfl_xor_sync(FULLM, a[i], 8);
        a[i] += __shfl_xor_sync(FULLM, a[i], 16);
    }
    if (lane < 8)
        *(float4*)&g_hn[n * 32 + 4 * lane] = make_float4(a[0], a[1], a[2], a[3]);
}

// ---------------- BatchNorm: partial sums + last-block finalize (acq_rel ticket, no L1 flush) ---
template <int DOUT>
__global__ void __launch_bounds__(256)
k_bn_partial(const float* __restrict__ gamma, const float* __restrict__ beta) {
    int tid = threadIdx.x;
    int c = tid % DOUT;
    float s = 0.f, q = 0.f;
    for (long i = (long)blockIdx.x * blockDim.x + tid; i < (long)NN * DOUT;
         i += (long)gridDim.x * blockDim.x) {
        float v = g_hn[i];
        s += v; q += v * v;
    }
    __shared__ float sm[256], qm[256];
    sm[tid] = s; qm[tid] = q;
    __syncthreads();
    for (int off = 128; off >= DOUT; off >>= 1) {
        if (tid < off) { sm[tid] += sm[tid + off]; qm[tid] += qm[tid + off]; }
        __syncthreads();
    }
    if (tid < DOUT) {
        atomicAdd(&g_bnsum[c], (double)sm[tid]);
        atomicAdd(&g_bnsq[c],  (double)qm[tid]);
    }
    // last-block finalize: release on ticket orders our atomics; acquire orders our reads.
    __shared__ bool isLast;
    if (tid == 0) isLast = (ticket_acq_rel(&g_tick) == gridDim.x - 1);
    __syncthreads();
    if (isLast) {
        if (tid == 0) g_tick = 0;
        if (tid < DOUT) {
            double ds = ld_cg_f64(&g_bnsum[tid]);   // L1-bypass read of L2-coherent atomics
            double dq = ld_cg_f64(&g_bnsq[tid]);
            float mean = (float)(ds / (double)NN);
            float var  = (float)(dq / (double)NN) - mean * mean;
            var = fmaxf(var, 0.f);
            float sc = gamma[tid] * rsqrtf(var + BN_EPS);
            g_scale[tid] = sc;
            g_shift[tid] = beta[tid] - mean * sc;
            g_bnsum[tid] = 0.0;
            g_bnsq[tid]  = 0.0;
        }
    }
}

// ---------------- fused: final BN apply + per-graph pooling + gemb + both heads ----------------
__global__ void __launch_bounds__(256)
k_pool_fused(const int* __restrict__ batch, float* __restrict__ out_h,
             float* __restrict__ out_gemb, float* __restrict__ out_eth,
             float* __restrict__ out_man,
             const float* __restrict__ ew1, const float* __restrict__ eb1,
             const float* __restrict__ ew2, const float* __restrict__ eb2,
             const float* __restrict__ mw1, const float* __restrict__ mb1,
             const float* __restrict__ mw2, const float* __restrict__ mb2) {
    int g = blockIdx.x;
    int t = threadIdx.x;
    int l = 0, r = NN;
    while (l < r) { int m = (l + r) >> 1; if (batch[m] < g) l = m + 1; else r = m; }
    int s0 = l;
    l = s0; r = NN;
    while (l < r) { int m = (l + r) >> 1; if (batch[m] < g + 1) l = m + 1; else r = m; }
    int s1 = l;

    int c = t % 32, row = t / 32;
    float sc = g_scale[c], shf = g_shift[c];
    float sum = 0.f, mx = -FLT_MAX;
    for (int n = s0 + row; n < s1; n += 8) {
        float v = fmaf(sc, g_hn[n * 32 + c], shf);
        out_h[n * 32 + c] = v;
        sum += v;
        mx = fmaxf(mx, v);
    }
    __shared__ float ssum[256], smax[256];
    __shared__ float ge[32];
    ssum[t] = sum; smax[t] = mx;
    __syncthreads();
    for (int o = 128; o >= 32; o >>= 1) {
        if (t < o) { ssum[t] += ssum[t + o]; smax[t] = fmaxf(smax[t], smax[t + o]); }
        __syncthreads();
    }
    if (t < 32) {
        float cnt = (float)(s1 - s0);
        float sm = ssum[t];
        float mean = sm / fmaxf(cnt, 1.f);
        float mxv = (cnt > 0.f) ? smax[t] : 0.f;
        float v = (mean + mxv + sm) * (1.f / 3.f);
        out_gemb[g * 32 + t] = v;
        ge[t] = v;
    }
    __syncthreads();
    if (t < 32) {
        const float* w1 = (t < 16) ? ew1 : mw1;
        const float* b1 = (t < 16) ? eb1 : mb1;
        const float* w2 = (t < 16) ? ew2 : mw2;
        const float* b2 = (t < 16) ? eb2 : mb2;
        int j = t & 15;
        float a = b1[j];
#pragma unroll
        for (int k = 0; k < 32; k++) a = fmaf(ge[k], w1[k * 16 + j], a);
        float contrib = fmaxf(a, 0.f) * w2[j];
#pragma unroll
        for (int o = 8; o; o >>= 1) contrib += __shfl_xor_sync(FULLM, contrib, o);
        if (j == 0) {
            float oo = contrib + b2[0];
            float sig = 1.f / (1.f + expf(-oo));
            if (t < 16) out_eth[g] = sig; else out_man[g] = sig;
        }
    }
}

// ---------------- host ----------------
extern "C" void kernel_launch(void* const* d_in, const int* in_sizes, int n_in,
                              void* d_out, int out_size) {
    const float* x      = (const float*)d_in[0];
    const int*   ei     = (const int*)d_in[1];
    const int*   batch  = (const int*)d_in[2];
    const float* enc_w  = (const float*)d_in[3];
    const float* enc_b  = (const float*)d_in[4];
    const float* W0 = (const float*)d_in[5],  *A0s = (const float*)d_in[6],  *A0d = (const float*)d_in[7];
    const float* G0 = (const float*)d_in[9],  *B0  = (const float*)d_in[10];
    const float* W1 = (const float*)d_in[11], *A1s = (const float*)d_in[12], *A1d = (const float*)d_in[13];
    const float* G1 = (const float*)d_in[15], *B1  = (const float*)d_in[16];
    const float* W2 = (const float*)d_in[17], *A2s = (const float*)d_in[18], *A2d = (const float*)d_in[19];
    const float* G2 = (const float*)d_in[21], *B2  = (const float*)d_in[22];
    const float* ew1 = (const float*)d_in[23], *eb1 = (const float*)d_in[24];
    const float* ew2 = (const float*)d_in[25], *eb2 = (const float*)d_in[26];
    const float* mw1 = (const float*)d_in[27], *mb1 = (const float*)d_in[28];
    const float* mw2 = (const float*)d_in[29], *mb2 = (const float*)d_in[30];

    float* out      = (float*)d_out;
    float* out_h    = out;
    float* out_gemb = out + (size_t)NN * OUTC;
    float* out_eth  = out_gemb + GG * OUTC;
    float* out_man  = out_eth + GG;

    void* phn;
    cudaGetSymbolAddress(&phn, g_hn);

    // CSR build (g_cnt self-zeroing via k_scan_c; zero at module load)
    k_hist<<<(ETOT + 255) / 256, 256>>>(ei);
    k_scan_a<<<49, 1024>>>();
    k_scan_b<<<1, 1>>>();
    k_scan_c<<<49, 1024>>>();
    k_fill<<<(ETOT + 255) / 256, 256>>>(ei);

    // Layer 0 (encoder fused into transform input stage)
    k_transform2<64, 0><<<(NN + 31) / 32, 256>>>(x, W0, A0s, A0d, enc_w, enc_b);
    k_agg64<<<(NN + 7) / 8, 256>>>();
    k_bn_partial<64><<<296, 256>>>(G0, B0);

    // Layer 1
    k_transform2<64, 1><<<(NN + 31) / 32, 256>>>((const float*)phn, W1, A1s, A1d, enc_w, enc_b);
    k_agg64<<<(NN + 7) / 8, 256>>>();
    k_bn_partial<64><<<296, 256>>>(G1, B1);

    // Layer 2
    k_transform2<32, 1><<<(NN + 63) / 64, 256>>>((const float*)phn, W2, A2s, A2d, enc_w, enc_b);
    k_agg32<<<(NN + 7) / 8, 256>>>();
    k_bn_partial<32><<<296, 256>>>(G2, B2);

    // Fused BN apply + pooling + gemb + heads
    k_pool_fused<<<GG, 256>>>(batch, out_h, out_gemb, out_eth, out_man,
                              ew1, eb1, ew2, eb2, mw1, mb1, mw2, mb2);
}